// round 13
// baseline (speedup 1.0000x reference)
#include <cuda_runtime.h>
#include <cstdint>

// out[s,b,o,hw] = sum_k adc_real[b,k,hw]*W[s*256+o,k] + adc_imag[b,k,hw]*W[s*256+o,256+k]
// GEMM D[512, 4*65536] = W[512,512] * X[512,*] via mma.sync tf32 HMMA.
// R13: whole-chunk register preload -> 64 dependency-free MMAs per warp per
// chunk (one LDS latency exposure per chunk instead of four). 256 thr, 8 warps,
// warp tile 64x32 (4Mx2N), CTA tile 256x64, 3-stage cp.async for W (pre-rounded
// RNA + k-pair-permuted) and X (HW tf32 pickup), direct STG.64 epilogue.

#define NFFT 256
#define HW   65536
#define KTOT 512
#define KC   32
#define MT   256                 // o rows per CTA
#define NT   64                  // hw cols per CTA
#define NSTG 3
#define XP   72                  // xs pitch (floats): banks 8tx+ty distinct
#define WP   40                  // ws pitch (floats): conflict-free LDS.64 phases
#define WS_STAGE (MT * WP)       // 10240 floats
#define XS_STAGE (KC * XP)       // 2304 floats

__device__ float wprep[16 * 512 * 32];   // [k-chunk][row][pos], tf32-RNA-rounded

static __device__ __forceinline__ float tf32r(float x) {
    float r; asm("cvt.rna.tf32.f32 %0, %1;" : "=f"(r) : "f"(x)); return r;
}
static __device__ __forceinline__ uint32_t smem_u32(const void* p) {
    uint32_t a;
    asm("{ .reg .u64 t; cvta.to.shared.u64 t, %1; cvt.u32.u64 %0, t; }" : "=r"(a) : "l"(p));
    return a;
}

#define CP_ASYNC16(d, s) asm volatile("cp.async.cg.shared.global [%0], [%1], 16;" :: "r"(d), "l"(s))
#define CP_COMMIT()      asm volatile("cp.async.commit_group;" ::: "memory")
#define CP_WAIT1()       asm volatile("cp.async.wait_group 1;" ::: "memory")

#define MMA_TF32(d0,d1,d2,d3, a0,a1,a2,a3, b0,b1)                              \
    asm volatile("mma.sync.aligned.m16n8k8.row.col.f32.tf32.tf32.f32 "         \
        "{%0,%1,%2,%3}, {%4,%5,%6,%7}, {%8,%9}, {%0,%1,%2,%3};"                \
        : "+f"(d0), "+f"(d1), "+f"(d2), "+f"(d3)                               \
        : "r"(a0), "r"(a1), "r"(a2), "r"(a3), "r"(b0), "r"(b1))

// prep: tf32-RNA-round W, store k-pair-permuted per 32-k chunk:
// within each 8-k group order [k0,k4,k1,k5,k2,k6,k3,k7] so (k,k+4) adjacent.
__global__ void prep_w_kernel(const float* __restrict__ w) {
    const int idx = blockIdx.x * 256 + threadIdx.x;
    const int row = idx >> 9;
    const int k   = idx & 511;
    const int kk  = k & 31;
    const int pos = ((kk >> 3) << 3) + 2 * (kk & 3) + ((kk & 7) >> 2);
    wprep[(((size_t)(k >> 5) * 512) + row) * 32 + pos] = tf32r(w[idx]);
}

__global__ __launch_bounds__(256, 1)
void fft_hmma_kernel(const float* __restrict__ xr,
                     const float* __restrict__ xi,
                     float* __restrict__ out) {
    extern __shared__ float smem[];
    float* ws = smem;
    float* xs = smem + NSTG * WS_STAGE;
    const uint32_t ws_u32 = smem_u32(ws);
    const uint32_t xs_u32 = smem_u32(xs);

    const int tid  = threadIdx.x;
    const int lane = tid & 31;
    const int wid  = tid >> 5;
    const int wr   = wid & 3;                 // M-warp: 4 x 64 = 256
    const int wc   = wid >> 2;                // N-warp: 2 x 32 = 64
    const int ty   = lane >> 2;
    const int tx   = lane & 3;

    const int c0 = blockIdx.x * NT;
    const int by = blockIdx.y;                // s-plane; o0 = by*256
    const int o0 = by * MT;
    const int b  = blockIdx.z;

    const size_t xbase = (size_t)b * NFFT * HW + c0;
    const float* wsrc0 = wprep + (size_t)o0 * 32;

    float acc[4][4][4];
    #pragma unroll
    for (int mt = 0; mt < 4; mt++)
        #pragma unroll
        for (int nt = 0; nt < 4; nt++)
            #pragma unroll
            for (int q = 0; q < 4; q++) acc[mt][nt][q] = 0.0f;

    // ---- prologue: chunks 0,1 for W and X via cp.async ----
    #pragma unroll
    for (int cpre = 0; cpre < 2; cpre++) {
        const float* src = wsrc0 + (size_t)cpre * 512 * 32;
        const uint32_t wdst = ws_u32 + cpre * (WS_STAGE * 4);
        #pragma unroll
        for (int p = 0; p < 8; p++) {          // 2048 16B pieces / 256 thr
            const int idx = p * 256 + tid;
            const int r = idx >> 3, j = idx & 7;
            CP_ASYNC16(wdst + r * (WP * 4) + j * 16, src + r * 32 + j * 4);
        }
        const float* xsrcp = xr + xbase + (size_t)(cpre * KC) * HW;
        const uint32_t xdst = xs_u32 + cpre * (XS_STAGE * 4);
        #pragma unroll
        for (int p = 0; p < 2; p++) {          // 512 16B pieces / 256 thr
            const int idx = p * 256 + tid;
            const int row = idx >> 4, c16 = idx & 15;
            CP_ASYNC16(xdst + row * (XP * 4) + c16 * 16,
                       xsrcp + (size_t)row * HW + c16 * 4);
        }
        CP_COMMIT();
    }

    const int abase = (wr * 64 + ty) * WP + 2 * tx;     // + mt*16*WP + kk*8
    const int bbase = tx * XP + wc * 32 + ty;           // + kk*8*XP + nt*8

    for (int i = 0; i < 16; i++) {
        CP_WAIT1();
        __syncthreads();

        const int ki = i + 2;
        if (ki < 16) {
            const float* src = wsrc0 + (size_t)ki * 512 * 32;
            const uint32_t wdst = ws_u32 + (ki % NSTG) * (WS_STAGE * 4);
            #pragma unroll
            for (int p = 0; p < 8; p++) {
                const int idx = p * 256 + tid;
                const int r = idx >> 3, j = idx & 7;
                CP_ASYNC16(wdst + r * (WP * 4) + j * 16, src + r * 32 + j * 4);
            }
            const float* xsrcp = ((ki < 8) ? xr : xi) + xbase + (size_t)((ki & 7) * KC) * HW;
            const uint32_t xdst = xs_u32 + (ki % NSTG) * (XS_STAGE * 4);
            #pragma unroll
            for (int p = 0; p < 2; p++) {
                const int idx = p * 256 + tid;
                const int row = idx >> 4, c16 = idx & 15;
                CP_ASYNC16(xdst + row * (XP * 4) + c16 * 16,
                           xsrcp + (size_t)row * HW + c16 * 4);
            }
        }
        CP_COMMIT();

        // ---- preload ALL fragments of chunk i into registers ----
        const float* wst = ws + (i % NSTG) * WS_STAGE;
        const float* xst = xs + (i % NSTG) * XS_STAGE;
        float2   a2[4][4][2];                  // [kk][mt][half]
        uint32_t bf[4][4][2];                  // [kk][nt][half]
        #pragma unroll
        for (int kk = 0; kk < 4; kk++) {
            #pragma unroll
            for (int mt = 0; mt < 4; mt++) {
                const float* ap = wst + abase + mt * (16 * WP) + kk * 8;
                a2[kk][mt][0] = *(const float2*)ap;             // rows ty   : (k,k+4)
                a2[kk][mt][1] = *(const float2*)(ap + 8 * WP);  // rows ty+8 : (k,k+4)
            }
            #pragma unroll
            for (int nt = 0; nt < 4; nt++) {
                const float* bp = xst + bbase + kk * (8 * XP) + nt * 8;
                bf[kk][nt][0] = __float_as_uint(bp[0]);
                bf[kk][nt][1] = __float_as_uint(bp[4 * XP]);
            }
        }

        // ---- 64 back-to-back MMAs (16 independent acc chains of length 4) ----
        #pragma unroll
        for (int kk = 0; kk < 4; kk++) {
            #pragma unroll
            for (int mt = 0; mt < 4; mt++) {
                const uint32_t a0 = __float_as_uint(a2[kk][mt][0].x);
                const uint32_t a1 = __float_as_uint(a2[kk][mt][1].x);
                const uint32_t a2r = __float_as_uint(a2[kk][mt][0].y);
                const uint32_t a3 = __float_as_uint(a2[kk][mt][1].y);
                #pragma unroll
                for (int nt = 0; nt < 4; nt++)
                    MMA_TF32(acc[mt][nt][0], acc[mt][nt][1], acc[mt][nt][2], acc[mt][nt][3],
                             a0, a1, a2r, a3, bf[kk][nt][0], bf[kk][nt][1]);
            }
        }
    }

    // ---- epilogue: direct STG.64 ----
    float* outp = out + ((size_t)(by * 4 + b) * NFFT) * (size_t)HW + c0 + wc * 32;
    #pragma unroll
    for (int mt = 0; mt < 4; mt++) {
        const int r0 = wr * 64 + mt * 16 + ty;
        #pragma unroll
        for (int nt = 0; nt < 4; nt++) {
            const int col = nt * 8 + tx * 2;
            float2 v0 = make_float2(acc[mt][nt][0], acc[mt][nt][1]);
            float2 v1 = make_float2(acc[mt][nt][2], acc[mt][nt][3]);
            *(float2*)(outp + (size_t)r0 * HW + col)       = v0;
            *(float2*)(outp + (size_t)(r0 + 8) * HW + col) = v1;
        }
    }
}

extern "C" void kernel_launch(void* const* d_in, const int* in_sizes, int n_in,
                              void* d_out, int out_size) {
    const float* xr = nullptr;
    const float* xi = nullptr;
    const float* w  = nullptr;
    for (int i = 0; i < n_in; i++) {
        if (in_sizes[i] == 4 * NFFT * HW) {
            if (!xr)      xr = (const float*)d_in[i];
            else if (!xi) xi = (const float*)d_in[i];
        } else if (in_sizes[i] == KTOT * KTOT) {
            w = (const float*)d_in[i];
        }
    }
    float* out = (float*)d_out;

    prep_w_kernel<<<1024, 256>>>(w);

    const int smem_bytes = NSTG * (WS_STAGE + XS_STAGE) * 4;   // 150,528
    cudaFuncSetAttribute(fft_hmma_kernel, cudaFuncAttributeMaxDynamicSharedMemorySize, smem_bytes);
    dim3 grid(HW / NT, 2, 4);   // (1024, 2, 4)
    fft_hmma_kernel<<<grid, 256, smem_bytes>>>(xr, xi, out);
}

// round 14
// speedup vs baseline: 1.7631x; 1.7631x over previous
#include <cuda_runtime.h>
#include <cuda_fp16.h>
#include <cstdint>

// out[s,b,o,hw] = sum_k adc_real[b,k,hw]*W[s*256+o,k] + adc_imag[b,k,hw]*W[s*256+o,256+k]
// GEMM D[512, 4*65536] = W[512,512] * X[512,*] via mma.sync m16n8k16 fp16
// (fp32 accumulate). fp16 == tf32 operand precision (11 mantissa bits) but
// 2x K per MMA -> tensor floor halves vs R9-R13.
// R14: R9 shell: 512 thr, 16 warps (4Mx4N), warp tile 64x32, CTA 256x128,
// 3-stage cp.async W (fp16 RNE + k-pair-permuted offline), register X fill
// (packs (k,k+1) half2 = B-frag layout), direct STG.64 epilogue.

#define NFFT 256
#define HW   65536
#define KTOT 512
#define KC   32
#define MT   256
#define NT   128
#define NSTG 3
#define WPH2 40                  // W row pitch in half2 (160B): banks ty*4+tx distinct
#define XPH2 136                 // X row pitch in half2 (544B): 136 mod 32 = 8
#define WS_STAGE_B (MT * WPH2 * 4)    // 40960 B
#define XS_STAGE_B (16 * XPH2 * 4)    // 8704 B  (16 k-pair rows)

__device__ __half wprep[16 * 512 * 32];   // [k-chunk][row][pos], fp16 RNE, permuted

static __device__ __forceinline__ uint32_t smem_u32(const void* p) {
    uint32_t a;
    asm("{ .reg .u64 t; cvta.to.shared.u64 t, %1; cvt.u32.u64 %0, t; }" : "=r"(a) : "l"(p));
    return a;
}

#define CP_ASYNC16(d, s) asm volatile("cp.async.cg.shared.global [%0], [%1], 16;" :: "r"(d), "l"(s))
#define CP_COMMIT()      asm volatile("cp.async.commit_group;" ::: "memory")
#define CP_WAIT1()       asm volatile("cp.async.wait_group 1;" ::: "memory")

#define MMA_F16(d0,d1,d2,d3, a0,a1,a2,a3, b0,b1)                               \
    asm volatile("mma.sync.aligned.m16n8k16.row.col.f32.f16.f16.f32 "          \
        "{%0,%1,%2,%3}, {%4,%5,%6,%7}, {%8,%9}, {%0,%1,%2,%3};"                \
        : "+f"(d0), "+f"(d1), "+f"(d2), "+f"(d3)                               \
        : "r"(a0), "r"(a1), "r"(a2), "r"(a3), "r"(b0), "r"(b1))

// prep: W -> fp16 (RNE), permuted so pairs (p, p+4) sit adjacently:
// within each 16-k group, pair p (k=2p,2p+1) goes to slot pp = 2*(p&3)+(p>>2).
__global__ void prep_w_kernel(const float* __restrict__ w) {
    const int idx = blockIdx.x * 256 + threadIdx.x;     // 0..262143
    const int row = idx >> 9;
    const int k   = idx & 511;
    const int kk  = k & 31;
    const int grp = kk >> 4;
    const int j   = kk & 15;
    const int pr  = j >> 1;
    const int lip = j & 1;
    const int pp  = 2 * (pr & 3) + (pr >> 2);
    const int pos = grp * 16 + pp * 2 + lip;            // half index within 32-half row
    wprep[(((size_t)(k >> 5) * 512) + row) * 32 + pos] = __float2half_rn(w[idx]);
}

__global__ __launch_bounds__(512, 1)
void fft_hmma_kernel(const float* __restrict__ xr,
                     const float* __restrict__ xi,
                     float* __restrict__ out) {
    extern __shared__ char smem[];
    char* ws = smem;                                // NSTG x WS_STAGE_B
    char* xs = smem + NSTG * WS_STAGE_B;            // NSTG x XS_STAGE_B
    const uint32_t ws_u32 = smem_u32(ws);

    const int tid  = threadIdx.x;
    const int lane = tid & 31;
    const int wid  = tid >> 5;
    const int wr   = wid & 3;                 // M-warp: 4 x 64 = 256
    const int wc   = wid >> 2;                // N-warp: 4 x 32 = 128
    const int ty   = lane >> 2;
    const int tx   = lane & 3;

    const int c0 = blockIdx.x * NT;
    const int by = blockIdx.y;                // s-plane; o0 = by*256
    const int o0 = by * MT;
    const int b  = blockIdx.z;

    // X fill roles: 16 pair-rows x 32 c-groups(of 4) = 512 pieces, 1/thread
    const int x_pr = tid >> 5;                // pair row 0..15 (k = 2*x_pr, +1)
    const int x_c4 = (tid & 31) * 4;          // c group
    const size_t xoff = (size_t)b * NFFT * HW + c0 + x_c4;

    const __half* wsrc0 = wprep + (size_t)o0 * 32;

    float acc[4][4][4];
    #pragma unroll
    for (int mt = 0; mt < 4; mt++)
        #pragma unroll
        for (int nt = 0; nt < 4; nt++)
            #pragma unroll
            for (int q = 0; q < 4; q++) acc[mt][nt][q] = 0.0f;

    float4 px0, px1;

    // ---- prologue: W chunks 0,1 via cp.async; X chunks 0,1 via registers ----
    #pragma unroll
    for (int cpre = 0; cpre < 2; cpre++) {
        const __half* src = wsrc0 + (size_t)cpre * 512 * 32;
        const uint32_t wdst = ws_u32 + cpre * WS_STAGE_B;
        #pragma unroll
        for (int p = 0; p < 2; p++) {          // 1024 16B pieces / 512 thr
            const int idx = p * 512 + tid;
            const int r = idx >> 2, j = idx & 3;
            CP_ASYNC16(wdst + r * (WPH2 * 4) + j * 16, src + r * 32 + j * 8);
        }
        CP_COMMIT();
    }
    #pragma unroll
    for (int cpre = 0; cpre < 2; cpre++) {
        const float* xsrcp = xr + xoff + (size_t)(cpre * KC) * HW;
        px0 = *(const float4*)(xsrcp + (size_t)(2 * x_pr) * HW);
        px1 = *(const float4*)(xsrcp + (size_t)(2 * x_pr + 1) * HW);
        __half2* xd = (__half2*)(xs + cpre * XS_STAGE_B) + x_pr * XPH2 + x_c4;
        __half2 h[4];
        h[0] = __floats2half2_rn(px0.x, px1.x);
        h[1] = __floats2half2_rn(px0.y, px1.y);
        h[2] = __floats2half2_rn(px0.z, px1.z);
        h[3] = __floats2half2_rn(px0.w, px1.w);
        *(uint4*)xd = *(uint4*)h;
    }

    // frag base offsets (half2 units)
    const int abase = (wr * 64 + ty) * WPH2 + 2 * tx;   // + mt*16*WPH2 + ks*8
    const int bbase = tx * XPH2 + wc * 32 + ty;         // + ks*8*XPH2 + nt*8

    for (int i = 0; i < 16; i++) {
        CP_WAIT1();
        __syncthreads();

        const int ki = i + 2;
        if (ki < 16) {
            const __half* src = wsrc0 + (size_t)ki * 512 * 32;
            const uint32_t wdst = ws_u32 + (ki % NSTG) * WS_STAGE_B;
            #pragma unroll
            for (int p = 0; p < 2; p++) {
                const int idx = p * 512 + tid;
                const int r = idx >> 2, j = idx & 3;
                CP_ASYNC16(wdst + r * (WPH2 * 4) + j * 16, src + r * 32 + j * 8);
            }
            const float* xsrcp = ((ki < 8) ? xr : xi) + xoff + (size_t)((ki & 7) * KC) * HW;
            px0 = *(const float4*)(xsrcp + (size_t)(2 * x_pr) * HW);
            px1 = *(const float4*)(xsrcp + (size_t)(2 * x_pr + 1) * HW);
        }
        CP_COMMIT();

        // ---- compute chunk i from stage i%3 (2 k-steps of 16) ----
        const __half2* wst = (const __half2*)(ws + (i % NSTG) * WS_STAGE_B);
        const __half2* xst = (const __half2*)(xs + (i % NSTG) * XS_STAGE_B);
        #pragma unroll
        for (int ks = 0; ks < 2; ks++) {
            uint2 aw[4][2];
            #pragma unroll
            for (int mt = 0; mt < 4; mt++) {
                const __half2* ap = wst + abase + mt * (16 * WPH2) + ks * 8;
                aw[mt][0] = *(const uint2*)ap;                    // (a0, a2) row ty
                aw[mt][1] = *(const uint2*)(ap + 8 * WPH2);       // (a1, a3) row ty+8
            }
            uint32_t bf[4][2];
            #pragma unroll
            for (int nt = 0; nt < 4; nt++) {
                const __half2* bp = xst + bbase + ks * (8 * XPH2) + nt * 8;
                bf[nt][0] = *(const uint32_t*)bp;                 // pairs (2tx,2tx+1)
                bf[nt][1] = *(const uint32_t*)(bp + 4 * XPH2);    // pairs (2tx+8,2tx+9)
            }
            #pragma unroll
            for (int mt = 0; mt < 4; mt++) {
                #pragma unroll
                for (int nt = 0; nt < 4; nt++)
                    MMA_F16(acc[mt][nt][0], acc[mt][nt][1], acc[mt][nt][2], acc[mt][nt][3],
                            aw[mt][0].x, aw[mt][1].x, aw[mt][0].y, aw[mt][1].y,
                            bf[nt][0], bf[nt][1]);
            }
        }

        // ---- X pack + STS chunk ki -> stage ki%3 ----
        if (ki < 16) {
            __half2* xd = (__half2*)(xs + (ki % NSTG) * XS_STAGE_B) + x_pr * XPH2 + x_c4;
            __half2 h[4];
            h[0] = __floats2half2_rn(px0.x, px1.x);
            h[1] = __floats2half2_rn(px0.y, px1.y);
            h[2] = __floats2half2_rn(px0.z, px1.z);
            h[3] = __floats2half2_rn(px0.w, px1.w);
            *(uint4*)xd = *(uint4*)h;
        }
    }

    // ---- epilogue: direct STG.64 (R9-verified layout) ----
    float* outp = out + ((size_t)(by * 4 + b) * NFFT) * (size_t)HW + c0 + wc * 32;
    #pragma unroll
    for (int mt = 0; mt < 4; mt++) {
        const int r0 = wr * 64 + mt * 16 + ty;
        #pragma unroll
        for (int nt = 0; nt < 4; nt++) {
            const int col = nt * 8 + tx * 2;
            float2 v0 = make_float2(acc[mt][nt][0], acc[mt][nt][1]);
            float2 v1 = make_float2(acc[mt][nt][2], acc[mt][nt][3]);
            *(float2*)(outp + (size_t)r0 * HW + col)       = v0;
            *(float2*)(outp + (size_t)(r0 + 8) * HW + col) = v1;
        }
    }
}

extern "C" void kernel_launch(void* const* d_in, const int* in_sizes, int n_in,
                              void* d_out, int out_size) {
    const float* xr = nullptr;
    const float* xi = nullptr;
    const float* w  = nullptr;
    for (int i = 0; i < n_in; i++) {
        if (in_sizes[i] == 4 * NFFT * HW) {
            if (!xr)      xr = (const float*)d_in[i];
            else if (!xi) xi = (const float*)d_in[i];
        } else if (in_sizes[i] == KTOT * KTOT) {
            w = (const float*)d_in[i];
        }
    }
    float* out = (float*)d_out;

    prep_w_kernel<<<1024, 256>>>(w);

    const int smem_bytes = NSTG * (WS_STAGE_B + XS_STAGE_B);   // 148,992
    cudaFuncSetAttribute(fft_hmma_kernel, cudaFuncAttributeMaxDynamicSharedMemorySize, smem_bytes);
    dim3 grid(HW / NT, 2, 4);   // (512, 2, 4)
    fft_hmma_kernel<<<grid, 512, smem_bytes>>>(xr, xi, out);
}